// round 15
// baseline (speedup 1.0000x reference)
#include <cuda_runtime.h>
#include <cuda_bf16.h>
#include <cstdint>
#include <math.h>

// Problem shapes (fixed)
#define NX 4096
#define NY 16384
#define CX 128
#define CY 128
#define OD 256
#define KIN 256
#define NB 8
#define BIGD 1e30f
#define W_EPS 1e-16f
#define LN_EPS 1e-5f

// Global scratch
__device__ __nv_bfloat16 g_Wh[OD * KIN];
__device__ __nv_bfloat16 g_Wl[OD * KIN];
__device__ float  g_sx[NX];      // per-batch x-sorted x coords
__device__ float4 g_sp4[NX];     // (y, z, |p|^2, idx_bits) in same order
__device__ int    g_badsort[NB];

// ---------------------------------------------------------------------------
// Helpers (baseline PTX, valid for compute_100)
// ---------------------------------------------------------------------------
static __device__ __forceinline__ uint32_t smem_u32(const void* p) {
    uint32_t a;
    asm("{ .reg .u64 t; cvta.to.shared.u64 t, %1; cvt.u32.u64 %0, t; }"
        : "=r"(a) : "l"(p));
    return a;
}

static __device__ __forceinline__ void ldsm_x4(uint32_t addr, uint32_t* r) {
    asm volatile("ldmatrix.sync.aligned.m8n8.x4.shared.b16 {%0,%1,%2,%3}, [%4];"
                 : "=r"(r[0]), "=r"(r[1]), "=r"(r[2]), "=r"(r[3]) : "r"(addr));
}

static __device__ __forceinline__ void mma_bf16(float* d, const uint32_t* a,
                                                uint32_t b0, uint32_t b1) {
    asm volatile(
        "mma.sync.aligned.m16n8k16.row.col.f32.bf16.bf16.f32 "
        "{%0,%1,%2,%3},{%4,%5,%6,%7},{%8,%9},{%0,%1,%2,%3};"
        : "+f"(d[0]), "+f"(d[1]), "+f"(d[2]), "+f"(d[3])
        : "r"(a[0]), "r"(a[1]), "r"(a[2]), "r"(a[3]), "r"(b0), "r"(b1));
}

static __device__ __forceinline__ void cp_async16(uint32_t dst, const void* src) {
    asm volatile("cp.async.cg.shared.global [%0], [%1], 16;" :: "r"(dst), "l"(src));
}
static __device__ __forceinline__ void cp_commit() {
    asm volatile("cp.async.commit_group;" ::: "memory");
}
template <int N>
static __device__ __forceinline__ void cp_wait() {
    asm volatile("cp.async.wait_group %0;" :: "n"(N) : "memory");
}

// Fast hi/lo bf16 split of a float pair
static __device__ __forceinline__ void split_pair(float v0, float v1,
                                                  uint32_t& hp, uint32_t& lp) {
    uint32_t u0 = __float_as_uint(v0), u1 = __float_as_uint(v1);
    asm("prmt.b32 %0, %1, %2, 0x7632;" : "=r"(hp) : "r"(u0), "r"(u1));
    float h0 = __uint_as_float(u0 & 0xFFFF0000u);
    float h1 = __uint_as_float(u1 & 0xFFFF0000u);
    float l0 = v0 - h0, l1 = v1 - h1;
    asm("cvt.rn.bf16x2.f32 %0, %1, %2;" : "=r"(lp) : "f"(l1), "f"(l0));
}

// Exact branchless top-3 insert
static __device__ __forceinline__ void ins3(float d, int j,
                                            float& d0, float& d1, float& d2,
                                            int& i0, int& i1, int& i2) {
    bool lt0 = d < d0, lt1 = d < d1, lt2 = d < d2;
    d2 = lt1 ? d1 : (lt2 ? d : d2); i2 = lt1 ? i1 : (lt2 ? j : i2);
    d1 = lt0 ? d0 : (lt1 ? d : d1); i1 = lt0 ? i0 : (lt1 ? j : i1);
    d0 = lt0 ? d  : d0;             i0 = lt0 ? j  : i0;
}

// ---------------------------------------------------------------------------
// Kernel 0 (prep): blocks 0-15 W split, 16-23 per-batch x-sort, 512 threads.
// ---------------------------------------------------------------------------
#define SORT_N 1024

__global__ __launch_bounds__(512)
void prep_kernel(const float* __restrict__ W,
                 const float* __restrict__ pos_x,
                 const int*   __restrict__ batch_x)
{
    const int tid = threadIdx.x;
    if (blockIdx.x < 16) {
        // W split: 16 blocks x 512 thr x 4 pairs = 32768 pairs
        int base = blockIdx.x * (512 * 4) + tid;
        uint32_t* wh = (uint32_t*)g_Wh;
        uint32_t* wl = (uint32_t*)g_Wl;
#pragma unroll
        for (int i = 0; i < 4; i++) {
            int p = base + i * 512;
            float2 v = *(const float2*)&W[p * 2];
            split_pair(v.x, v.y, wh[p], wl[p]);
        }
        return;
    }

    // ---- per-batch bitonic sort by x ----
    const int b = (int)blockIdx.x - 16;
    __shared__ float kx[SORT_N], ky[SORT_N], kz[SORT_N], kn[SORT_N];
    __shared__ int   ki[SORT_N];
    __shared__ int sse[2];
    if (tid < 2) {
        int t = b + tid;
        int lo = 0, hi = NX;
        while (lo < hi) { int m = (lo + hi) >> 1; if (batch_x[m] < t) lo = m + 1; else hi = m; }
        sse[tid] = lo;
    }
    __syncthreads();
    const int s = sse[0], e = sse[1], n = e - s;

    if (n > SORT_N) {
        // passthrough unsorted; mark bad
        if (tid == 0) g_badsort[b] = 1;
        for (int i = tid; i < n; i += 512) {
            int j = s + i;
            float x = pos_x[j * 3], y = pos_x[j * 3 + 1], z = pos_x[j * 3 + 2];
            g_sx[j] = x;
            g_sp4[j] = make_float4(y, z, x * x + y * y + z * z, __int_as_float(j));
        }
        return;
    }
    if (tid == 0) g_badsort[b] = 0;

    for (int i = tid; i < SORT_N; i += 512) {
        if (i < n) {
            int j = s + i;
            float x = pos_x[j * 3], y = pos_x[j * 3 + 1], z = pos_x[j * 3 + 2];
            kx[i] = x; ky[i] = y; kz[i] = z;
            kn[i] = x * x + y * y + z * z;
            ki[i] = j;
        } else {
            kx[i] = BIGD; ky[i] = 0.f; kz[i] = 0.f; kn[i] = 0.f; ki[i] = 0;
        }
    }
    __syncthreads();

    for (int k = 2; k <= SORT_N; k <<= 1) {
        for (int jj = k >> 1; jj > 0; jj >>= 1) {
            for (int i = tid; i < SORT_N; i += 512) {
                int l = i ^ jj;
                if (l > i) {
                    bool up = ((i & k) == 0);
                    if ((kx[i] > kx[l]) == up) {
                        float t;
                        t = kx[i]; kx[i] = kx[l]; kx[l] = t;
                        t = ky[i]; ky[i] = ky[l]; ky[l] = t;
                        t = kz[i]; kz[i] = kz[l]; kz[l] = t;
                        t = kn[i]; kn[i] = kn[l]; kn[l] = t;
                        int ti = ki[i]; ki[i] = ki[l]; ki[l] = ti;
                    }
                }
            }
            __syncthreads();
        }
    }

    for (int i = tid; i < n; i += 512) {
        g_sx[s + i] = kx[i];
        g_sp4[s + i] = make_float4(ky[i], kz[i], kn[i], __int_as_float(ki[i]));
    }
}

// ---------------------------------------------------------------------------
// Kernel 1 (FUSED): pruned quad-KNN + interp -> A tile -> 3-term bf16 hi/lo
// GEMM -> LN + ReLU.  128 CTAs x 512 thr, GEMM 16 warps (2m x 8n).
// SMEM (217088): A_hi@0, A_lo@67584, B buf0@135168, buf1/POS@176128
//   POS stage (pruned path): sxA[2048] f32 @176128 (8192), sp4A[2048] f4
//   @184320 (32768) -> exactly fills buf1 (40960).
// ---------------------------------------------------------------------------
#define SROW 528
#define A_HI 0
#define A_LO 67584
#define POSB 135168
#define BSTR 80
#define BBUF 40960
#define BLOF 20480
#define G_TOTAL 217088
#define WMAX 2048

__global__ __launch_bounds__(512, 1)
void fused_kernel(const float* __restrict__ pos_y,
                  const float* __restrict__ xfeat,
                  const int*   __restrict__ batch_x,
                  const float* __restrict__ yfeat,
                  const int*   __restrict__ batch_y,
                  const float* __restrict__ gamma,
                  const float* __restrict__ beta,
                  float* __restrict__ out)
{
    extern __shared__ char smem[];
    const uint32_t sb = smem_u32(smem);
    __shared__ int sbounds[9];
    __shared__ int sflags;

    const int tid  = threadIdx.x;
    const int wid  = tid >> 5;
    const int lane = tid & 31;
    const int rowBase = blockIdx.x * 128;

    if (tid < 9) {
        int t = tid;
        int lo = 0, hi = NX;
        while (lo < hi) { int m = (lo + hi) >> 1; if (batch_x[m] < t) lo = m + 1; else hi = m; }
        sbounds[t] = lo;
    }
    __syncthreads();

    const int bmin = batch_y[rowBase];
    const int bmax = batch_y[rowBase + 127];
    const int s0   = sbounds[bmin];
    const int n    = sbounds[bmax + 1] - s0;

    if (tid == 0) {
        int bad = 0;
        for (int b = bmin; b <= bmax; b++) bad |= g_badsort[b];
        sflags = bad;
    }

    // ---- B phase loader ----
    auto load_B = [&](int p, uint32_t bb) {
        const int kof = p * 32;
#pragma unroll
        for (int i = 0; i < 2; i++) {
            int idx = tid + i * 512;
            int r = idx >> 2, kc = idx & 3;
            const size_t gs = (size_t)r * KIN + kof + kc * 8;
            uint32_t off = (uint32_t)(r * BSTR + kc * 16);
            cp_async16(bb + off, &g_Wh[gs]);
            cp_async16(bb + BLOF + off, &g_Wl[gs]);
        }
        cp_commit();
    };

    load_B(0, sb + POSB);                  // prefetch B(0) into buf0 during KNN

    float* sxA  = (float*)(smem + POSB + BBUF);            // [2048]
    float4* sp4A = (float4*)(smem + POSB + BBUF + 8192);   // [2048]

    const bool fit = (n <= WMAX);
    if (fit) {
        for (int i = tid; i < n; i += 512) {
            sxA[i] = g_sx[s0 + i];
            sp4A[i] = g_sp4[s0 + i];
        }
    }
    __syncthreads();
    const bool pruned = fit && (sflags == 0);

    // ---- KNN: 4 threads per query ----
    {
        const int qIdx = tid >> 2;          // 0..127 local row
        const int g4   = tid & 3;
        const int yi   = rowBase + qIdx;

        const float qx = pos_y[yi * 3 + 0];
        const float qy = pos_y[yi * 3 + 1];
        const float qz = pos_y[yi * 3 + 2];
        const float qn = qx * qx + qy * qy + qz * qz;
        const int b = batch_y[yi];
        const int s = sbounds[b], e = sbounds[b + 1];

        float d0 = BIGD, d1 = BIGD, d2v = BIGD;
        int   i0 = 0,    i1 = 0,    i2 = 0;

        if (pruned) {
            const int ls = s - s0, le = e - s0;
            // lower bound of qx in sxA[ls, le)
            int lo = ls, hi = le;
            while (lo < hi) { int m = (lo + hi) >> 1; if (sxA[m] < qx) lo = m + 1; else hi = m; }
            const int pos = lo;
            int j, stride;
            if (g4 < 2) { j = pos - 1 - (g4 & 1); stride = -2; }
            else        { j = pos + (g4 & 1);     stride = 2;  }
            const unsigned span = (unsigned)(le - ls);
            while ((unsigned)(j - ls) < span) {
                float dx = sxA[j] - qx;
                if (dx * dx > d2v + 4e-6f) break;   // exact-safe prune
                float4 p = sp4A[j];
                float d = fmaxf(qn + p.z - 2.0f * (qx * sxA[j] + qy * p.x + qz * p.y), 0.0f);
                ins3(d, __float_as_int(p.w), d0, d1, d2v, i0, i1, i2);
                j += stride;
            }
        } else {
            for (int j = s + g4; j < e; j += 4) {
                float xj = g_sx[j];
                float4 p = g_sp4[j];
                float d = fmaxf(qn + p.z - 2.0f * (qx * xj + qy * p.x + qz * p.y), 0.0f);
                ins3(d, __float_as_int(p.w), d0, d1, d2v, i0, i1, i2);
            }
        }

        // quad merge (xor 1, xor 2 — all 4 lanes converge)
#pragma unroll
        for (int off = 1; off <= 2; off <<= 1) {
            float od0 = __shfl_xor_sync(0xffffffffu, d0,  off);
            float od1 = __shfl_xor_sync(0xffffffffu, d1,  off);
            float od2 = __shfl_xor_sync(0xffffffffu, d2v, off);
            int   oi0 = __shfl_xor_sync(0xffffffffu, i0,  off);
            int   oi1 = __shfl_xor_sync(0xffffffffu, i1,  off);
            int   oi2 = __shfl_xor_sync(0xffffffffu, i2,  off);
            ins3(od0, oi0, d0, d1, d2v, i0, i1, i2);
            ins3(od1, oi1, d0, d1, d2v, i0, i1, i2);
            ins3(od2, oi2, d0, d1, d2v, i0, i1, i2);
        }

        const float w0 = 1.0f / fmaxf(d0,  W_EPS);
        const float w1 = 1.0f / fmaxf(d1,  W_EPS);
        const float w2 = 1.0f / fmaxf(d2v, W_EPS);
        const float inv_wsum = 1.0f / (w0 + w1 + w2);

        const float* f0 = xfeat + (size_t)i0 * CX;
        const float* f1 = xfeat + (size_t)i1 * CX;
        const float* f2 = xfeat + (size_t)i2 * CX;
        const float* fy = yfeat + (size_t)yi * CY;

        // each quad thread: 8 chunks of 4 cols (c = g4*4 + i*16)
#pragma unroll
        for (int i = 0; i < 8; i++) {
            const int c = g4 * 4 + i * 16;
            float4 a0 = *(const float4*)&f0[c];
            float4 a1 = *(const float4*)&f1[c];
            float4 a2 = *(const float4*)&f2[c];
            float4 ay = *(const float4*)&fy[c];
            float v0 = (w0 * a0.x + w1 * a1.x + w2 * a2.x) * inv_wsum;
            float v1 = (w0 * a0.y + w1 * a1.y + w2 * a2.y) * inv_wsum;
            float v2 = (w0 * a0.z + w1 * a1.z + w2 * a2.z) * inv_wsum;
            float v3 = (w0 * a0.w + w1 * a1.w + w2 * a2.w) * inv_wsum;
            const uint32_t arow = (uint32_t)(qIdx * SROW + c * 2);
            uint2 hp, lp;
            split_pair(v0, v1, hp.x, lp.x);
            split_pair(v2, v3, hp.y, lp.y);
            *(uint2*)(smem + A_HI + arow) = hp;
            *(uint2*)(smem + A_LO + arow) = lp;
            split_pair(ay.x, ay.y, hp.x, lp.x);
            split_pair(ay.z, ay.w, hp.y, lp.y);
            *(uint2*)(smem + A_HI + arow + 256) = hp;
            *(uint2*)(smem + A_LO + arow + 256) = lp;
        }
    }
    __syncthreads();                       // A complete; pos region free for B

    // ---- GEMM mainloop: 8 phases of K=32 (identical to R13) ----
    const int g   = lane >> 2;
    const int tig = lane & 3;
    const int mw  = (wid >> 3) * 64;
    const int nw  = wid & 7;

    const int quad  = lane >> 3;
    const int lrow  = lane & 7;
    const int aRow  = (quad & 1) * 8 + lrow;
    const int aKoff = (quad >> 1) * 8;
    const int bRow  = ((lane >> 4) * 8) + lrow;
    const int bKoff = ((lane >> 3) & 1) * 8;
    const uint32_t offB = (uint32_t)((nw * 32 + bRow) * BSTR + bKoff * 2);
    const uint32_t aCol = (uint32_t)((mw + aRow) * SROW + aKoff * 2);

    float acc[4][4][4];
#pragma unroll
    for (int mt = 0; mt < 4; mt++)
#pragma unroll
        for (int nt = 0; nt < 4; nt++)
#pragma unroll
            for (int j = 0; j < 4; j++) acc[mt][nt][j] = 0.f;

#pragma unroll 1
    for (int p = 0; p < 8; p++) {
        if (p < 7) {
            load_B(p + 1, sb + POSB + (uint32_t)((p + 1) & 1) * BBUF);
            cp_wait<1>();
        } else {
            cp_wait<0>();
        }
        __syncthreads();

        const uint32_t bB = sb + POSB + (uint32_t)(p & 1) * BBUF + offB;
        const uint32_t aB = sb + A_HI + aCol + (uint32_t)(p * 64);

#pragma unroll
        for (int ks = 0; ks < 2; ks++) {
            const uint32_t kb = (uint32_t)(ks * 32);
            uint32_t Bh[8], Bl[8];
            ldsm_x4(bB + kb, Bh);
            ldsm_x4(bB + 1280 + kb, Bh + 4);
            ldsm_x4(bB + BLOF + kb, Bl);
            ldsm_x4(bB + BLOF + 1280 + kb, Bl + 4);
#pragma unroll
            for (int mt = 0; mt < 4; mt++) {
                uint32_t Ah[4], Al[4];
                const uint32_t aa = aB + (uint32_t)(mt * 16 * SROW) + kb;
                ldsm_x4(aa, Ah);
                ldsm_x4(aa + A_LO, Al);
#pragma unroll
                for (int nt = 0; nt < 4; nt++)
                    mma_bf16(acc[mt][nt], Ah, Bh[2 * nt], Bh[2 * nt + 1]);
#pragma unroll
                for (int nt = 0; nt < 4; nt++)
                    mma_bf16(acc[mt][nt], Al, Bh[2 * nt], Bh[2 * nt + 1]);
#pragma unroll
                for (int nt = 0; nt < 4; nt++)
                    mma_bf16(acc[mt][nt], Ah, Bl[2 * nt], Bl[2 * nt + 1]);
            }
        }
        __syncthreads();
    }

    // ---- LayerNorm stats (overlay B region) ----
    float* sSum = (float*)(smem + POSB);
    float* sSq  = sSum + 1024;
    float* sMu  = sSq + 1024;
    float* sRs  = sMu + 128;

#pragma unroll
    for (int mt = 0; mt < 4; mt++)
#pragma unroll
        for (int half = 0; half < 2; half++) {
            float s = 0.f, q = 0.f;
#pragma unroll
            for (int nt = 0; nt < 4; nt++)
#pragma unroll
                for (int j = 0; j < 2; j++) {
                    float v = acc[mt][nt][half * 2 + j];
                    s += v; q += v * v;
                }
            s += __shfl_xor_sync(0xffffffffu, s, 1);
            q += __shfl_xor_sync(0xffffffffu, q, 1);
            s += __shfl_xor_sync(0xffffffffu, s, 2);
            q += __shfl_xor_sync(0xffffffffu, q, 2);
            if (tig == 0) {
                int row = mw + mt * 16 + half * 8 + g;
                sSum[row * 8 + nw] = s;
                sSq[row * 8 + nw]  = q;
            }
        }
    __syncthreads();

    if (tid < 128) {
        float s = 0.f, q = 0.f;
#pragma unroll
        for (int i = 0; i < 8; i++) { s += sSum[tid * 8 + i]; q += sSq[tid * 8 + i]; }
        float mu = s * (1.0f / OD);
        float var = fmaxf(q * (1.0f / OD) - mu * mu, 0.0f);
        sMu[tid] = mu;
        sRs[tid] = rsqrtf(var + LN_EPS);
    }
    __syncthreads();

    // ---- normalize + affine + ReLU + store ----
#pragma unroll
    for (int mt = 0; mt < 4; mt++)
#pragma unroll
        for (int half = 0; half < 2; half++) {
            int row = mw + mt * 16 + half * 8 + g;
            float mu = sMu[row];
            float rs = sRs[row];
            float* orow = out + (size_t)(rowBase + row) * OD;
#pragma unroll
            for (int nt = 0; nt < 4; nt++) {
                int col = nw * 32 + nt * 8 + tig * 2;
                float2 gb0 = *(const float2*)&gamma[col];
                float2 bb0 = *(const float2*)&beta[col];
                float v0 = acc[mt][nt][half * 2 + 0];
                float v1 = acc[mt][nt][half * 2 + 1];
                float2 r2;
                r2.x = fmaxf((v0 - mu) * rs * gb0.x + bb0.x, 0.0f);
                r2.y = fmaxf((v1 - mu) * rs * gb0.y + bb0.y, 0.0f);
                *(float2*)&orow[col] = r2;
            }
        }
}

// ---------------------------------------------------------------------------
extern "C" void kernel_launch(void* const* d_in, const int* in_sizes, int n_in,
                              void* d_out, int out_size)
{
    const float* pos_x   = (const float*)d_in[0];
    const float* xfeat   = (const float*)d_in[1];
    const int*   batch_x = (const int*)  d_in[2];
    const float* pos_y   = (const float*)d_in[3];
    const float* yfeat   = (const float*)d_in[4];
    const int*   batch_y = (const int*)  d_in[5];
    const float* W       = (const float*)d_in[6];
    const float* gamma   = (const float*)d_in[7];
    const float* beta    = (const float*)d_in[8];
    float* out = (float*)d_out;

    prep_kernel<<<24, 512>>>(W, pos_x, batch_x);

    cudaFuncSetAttribute(fused_kernel,
                         cudaFuncAttributeMaxDynamicSharedMemorySize, G_TOTAL);
    fused_kernel<<<NY / 128, 512, G_TOTAL>>>(pos_y, xfeat, batch_x, yfeat,
                                             batch_y, gamma, beta, out);
}

// round 16
// speedup vs baseline: 1.0563x; 1.0563x over previous
#include <cuda_runtime.h>
#include <cuda_bf16.h>
#include <cstdint>
#include <math.h>

// Problem shapes (fixed)
#define NX 4096
#define NY 16384
#define CX 128
#define CY 128
#define OD 256
#define KIN 256
#define NB 8
#define BIGD 1e30f
#define W_EPS 1e-16f
#define LN_EPS 1e-5f

// Global scratch
__device__ __nv_bfloat16 g_Ah[NY * KIN];
__device__ __nv_bfloat16 g_Al[NY * KIN];
__device__ __nv_bfloat16 g_Wh[OD * KIN];
__device__ __nv_bfloat16 g_Wl[OD * KIN];
__device__ float  g_sx[NX];      // per-batch x-sorted x coords
__device__ float4 g_sp4[NX];     // (y, z, |p|^2, idx_bits) same order
__device__ int    g_badsort[NB];

// ---------------------------------------------------------------------------
// Helpers (baseline PTX, valid for compute_100)
// ---------------------------------------------------------------------------
static __device__ __forceinline__ uint32_t smem_u32(const void* p) {
    uint32_t a;
    asm("{ .reg .u64 t; cvta.to.shared.u64 t, %1; cvt.u32.u64 %0, t; }"
        : "=r"(a) : "l"(p));
    return a;
}

static __device__ __forceinline__ void ldsm_x4(uint32_t addr, uint32_t* r) {
    asm volatile("ldmatrix.sync.aligned.m8n8.x4.shared.b16 {%0,%1,%2,%3}, [%4];"
                 : "=r"(r[0]), "=r"(r[1]), "=r"(r[2]), "=r"(r[3]) : "r"(addr));
}

static __device__ __forceinline__ void mma_bf16(float* d, const uint32_t* a,
                                                uint32_t b0, uint32_t b1) {
    asm volatile(
        "mma.sync.aligned.m16n8k16.row.col.f32.bf16.bf16.f32 "
        "{%0,%1,%2,%3},{%4,%5,%6,%7},{%8,%9},{%0,%1,%2,%3};"
        : "+f"(d[0]), "+f"(d[1]), "+f"(d[2]), "+f"(d[3])
        : "r"(a[0]), "r"(a[1]), "r"(a[2]), "r"(a[3]), "r"(b0), "r"(b1));
}

static __device__ __forceinline__ void cp_async16(uint32_t dst, const void* src) {
    asm volatile("cp.async.cg.shared.global [%0], [%1], 16;" :: "r"(dst), "l"(src));
}
static __device__ __forceinline__ void cp_commit() {
    asm volatile("cp.async.commit_group;" ::: "memory");
}
template <int N>
static __device__ __forceinline__ void cp_wait() {
    asm volatile("cp.async.wait_group %0;" :: "n"(N) : "memory");
}

// Fast hi/lo bf16 split of a float pair
static __device__ __forceinline__ void split_pair(float v0, float v1,
                                                  uint32_t& hp, uint32_t& lp) {
    uint32_t u0 = __float_as_uint(v0), u1 = __float_as_uint(v1);
    asm("prmt.b32 %0, %1, %2, 0x7632;" : "=r"(hp) : "r"(u0), "r"(u1));
    float h0 = __uint_as_float(u0 & 0xFFFF0000u);
    float h1 = __uint_as_float(u1 & 0xFFFF0000u);
    float l0 = v0 - h0, l1 = v1 - h1;
    asm("cvt.rn.bf16x2.f32 %0, %1, %2;" : "=r"(lp) : "f"(l1), "f"(l0));
}

// Exact branchless top-3 insert
static __device__ __forceinline__ void ins3(float d, int j,
                                            float& d0, float& d1, float& d2,
                                            int& i0, int& i1, int& i2) {
    bool lt0 = d < d0, lt1 = d < d1, lt2 = d < d2;
    d2 = lt1 ? d1 : (lt2 ? d : d2); i2 = lt1 ? i1 : (lt2 ? j : i2);
    d1 = lt0 ? d0 : (lt1 ? d : d1); i1 = lt0 ? i0 : (lt1 ? j : i1);
    d0 = lt0 ? d  : d0;             i0 = lt0 ? j  : i0;
}

// ---------------------------------------------------------------------------
// Kernel 0: blocks 0-7 W split; blocks 8-15 per-batch x-sort (1024 thr,
// 1 element per thread -> cheap bitonic steps).
// ---------------------------------------------------------------------------
#define SORT_N 1024

__global__ __launch_bounds__(1024)
void prep_kernel(const float* __restrict__ W,
                 const float* __restrict__ pos_x,
                 const int*   __restrict__ batch_x)
{
    const int tid = threadIdx.x;
    if (blockIdx.x < 8) {
        int base = blockIdx.x * (1024 * 4) + tid;
        uint32_t* wh = (uint32_t*)g_Wh;
        uint32_t* wl = (uint32_t*)g_Wl;
#pragma unroll
        for (int i = 0; i < 4; i++) {
            int p = base + i * 1024;
            float2 v = *(const float2*)&W[p * 2];
            split_pair(v.x, v.y, wh[p], wl[p]);
        }
        return;
    }

    const int b = (int)blockIdx.x - 8;
    __shared__ float kx[SORT_N], ky[SORT_N], kz[SORT_N], kn[SORT_N];
    __shared__ int   ki[SORT_N];
    __shared__ int sse[2];
    if (tid < 2) {
        int t = b + tid;
        int lo = 0, hi = NX;
        while (lo < hi) { int m = (lo + hi) >> 1; if (batch_x[m] < t) lo = m + 1; else hi = m; }
        sse[tid] = lo;
    }
    __syncthreads();
    const int s = sse[0], e = sse[1], n = e - s;

    if (n > SORT_N) {
        if (tid == 0) g_badsort[b] = 1;
        for (int i = tid; i < n; i += 1024) {
            int j = s + i;
            float x = pos_x[j * 3], y = pos_x[j * 3 + 1], z = pos_x[j * 3 + 2];
            g_sx[j] = x;
            g_sp4[j] = make_float4(y, z, x * x + y * y + z * z, __int_as_float(j));
        }
        return;
    }
    if (tid == 0) g_badsort[b] = 0;

    {
        int i = tid;
        if (i < n) {
            int j = s + i;
            float x = pos_x[j * 3], y = pos_x[j * 3 + 1], z = pos_x[j * 3 + 2];
            kx[i] = x; ky[i] = y; kz[i] = z;
            kn[i] = x * x + y * y + z * z;
            ki[i] = j;
        } else {
            kx[i] = BIGD; ky[i] = 0.f; kz[i] = 0.f; kn[i] = 0.f; ki[i] = 0;
        }
    }
    __syncthreads();

    for (int k = 2; k <= SORT_N; k <<= 1) {
        for (int jj = k >> 1; jj > 0; jj >>= 1) {
            int l = tid ^ jj;
            if (l > tid) {
                bool up = ((tid & k) == 0);
                if ((kx[tid] > kx[l]) == up) {
                    float t;
                    t = kx[tid]; kx[tid] = kx[l]; kx[l] = t;
                    t = ky[tid]; ky[tid] = ky[l]; ky[l] = t;
                    t = kz[tid]; kz[tid] = kz[l]; kz[l] = t;
                    t = kn[tid]; kn[tid] = kn[l]; kn[l] = t;
                    int ti = ki[tid]; ki[tid] = ki[l]; ki[l] = ti;
                }
            }
            __syncthreads();
        }
    }

    if (tid < n) {
        g_sx[s + tid] = kx[tid];
        g_sp4[s + tid] = make_float4(ky[tid], kz[tid], kn[tid], __int_as_float(ki[tid]));
    }
}

// ---------------------------------------------------------------------------
// Kernel 1: pruned quad-KNN + interp -> g_Ah/g_Al (bf16 hi/lo).
// 256 blocks x 256 thr; block handles 64 queries (4 threads each).
// ---------------------------------------------------------------------------
#define WMAX 2048

__global__ __launch_bounds__(256)
void knn_kernel(const float* __restrict__ pos_y,
                const float* __restrict__ xfeat,
                const int*   __restrict__ batch_x,
                const float* __restrict__ yfeat,
                const int*   __restrict__ batch_y)
{
    __shared__ float  sxA[WMAX];
    __shared__ float4 sp4A[WMAX];
    __shared__ int sbounds[9];
    __shared__ int sflags;

    const int tid = threadIdx.x;
    if (tid < 9) {
        int t = tid;
        int lo = 0, hi = NX;
        while (lo < hi) { int m = (lo + hi) >> 1; if (batch_x[m] < t) lo = m + 1; else hi = m; }
        sbounds[t] = lo;
    }
    __syncthreads();

    const int q0   = blockIdx.x * 64;
    const int bmin = batch_y[q0];
    const int bmax = batch_y[q0 + 63];
    const int s0   = sbounds[bmin];
    const int n    = sbounds[bmax + 1] - s0;

    if (tid == 0) {
        int bad = 0;
        for (int b = bmin; b <= bmax; b++) bad |= g_badsort[b];
        sflags = bad;
    }

    const bool fit = (n <= WMAX);
    if (fit) {
        for (int i = tid; i < n; i += 256) {
            sxA[i] = g_sx[s0 + i];
            sp4A[i] = g_sp4[s0 + i];
        }
    }
    __syncthreads();
    const bool pruned = fit && (sflags == 0);

    const int qIdx = tid >> 2;           // 0..63
    const int g4   = tid & 3;
    const int yi   = q0 + qIdx;

    const float qx = pos_y[yi * 3 + 0];
    const float qy = pos_y[yi * 3 + 1];
    const float qz = pos_y[yi * 3 + 2];
    const float qn = qx * qx + qy * qy + qz * qz;
    const int b = batch_y[yi];
    const int s = sbounds[b], e = sbounds[b + 1];

    float d0 = BIGD, d1 = BIGD, d2v = BIGD;
    int   i0 = 0,    i1 = 0,    i2 = 0;

    if (pruned) {
        const int ls = s - s0, le = e - s0;
        int lo = ls, hi = le;
        while (lo < hi) { int m = (lo + hi) >> 1; if (sxA[m] < qx) lo = m + 1; else hi = m; }
        const int pos = lo;
        int j, stride;
        if (g4 < 2) { j = pos - 1 - (g4 & 1); stride = -2; }
        else        { j = pos + (g4 & 1);     stride = 2;  }
        const unsigned span = (unsigned)(le - ls);
        while ((unsigned)(j - ls) < span) {
            float dx = sxA[j] - qx;
            if (dx * dx > d2v + 4e-6f) break;
            float4 p = sp4A[j];
            float d = fmaxf(qn + p.z - 2.0f * (qx * sxA[j] + qy * p.x + qz * p.y), 0.0f);
            ins3(d, __float_as_int(p.w), d0, d1, d2v, i0, i1, i2);
            j += stride;
        }
    } else {
        for (int j = s + g4; j < e; j += 4) {
            float xj = g_sx[j];
            float4 p = g_sp4[j];
            float d = fmaxf(qn + p.z - 2.0f * (qx * xj + qy * p.x + qz * p.y), 0.0f);
            ins3(d, __float_as_int(p.w), d0, d1, d2v, i0, i1, i2);
        }
    }

#pragma unroll
    for (int off = 1; off <= 2; off <<= 1) {
        float od0 = __shfl_xor_sync(0xffffffffu, d0,  off);
        float od1 = __shfl_xor_sync(0xffffffffu, d1,  off);
        float od2 = __shfl_xor_sync(0xffffffffu, d2v, off);
        int   oi0 = __shfl_xor_sync(0xffffffffu, i0,  off);
        int   oi1 = __shfl_xor_sync(0xffffffffu, i1,  off);
        int   oi2 = __shfl_xor_sync(0xffffffffu, i2,  off);
        ins3(od0, oi0, d0, d1, d2v, i0, i1, i2);
        ins3(od1, oi1, d0, d1, d2v, i0, i1, i2);
        ins3(od2, oi2, d0, d1, d2v, i0, i1, i2);
    }

    const float w0 = 1.0f / fmaxf(d0,  W_EPS);
    const float w1 = 1.0f / fmaxf(d1,  W_EPS);
    const float w2 = 1.0f / fmaxf(d2v, W_EPS);
    const float inv_wsum = 1.0f / (w0 + w1 + w2);

    const float* f0 = xfeat + (size_t)i0 * CX;
    const float* f1 = xfeat + (size_t)i1 * CX;
    const float* f2 = xfeat + (size_t)i2 * CX;
    const float* fy = yfeat + (size_t)yi * CY;
    uint2* ah = (uint2*)(g_Ah + (size_t)yi * KIN);
    uint2* al = (uint2*)(g_Al + (size_t)yi * KIN);

#pragma unroll
    for (int i = 0; i < 8; i++) {
        const int c = g4 * 4 + i * 16;
        float4 a0 = *(const float4*)&f0[c];
        float4 a1 = *(const float4*)&f1[c];
        float4 a2 = *(const float4*)&f2[c];
        float4 ay = *(const float4*)&fy[c];
        float v0 = (w0 * a0.x + w1 * a1.x + w2 * a2.x) * inv_wsum;
        float v1 = (w0 * a0.y + w1 * a1.y + w2 * a2.y) * inv_wsum;
        float v2 = (w0 * a0.z + w1 * a1.z + w2 * a2.z) * inv_wsum;
        float v3 = (w0 * a0.w + w1 * a1.w + w2 * a2.w) * inv_wsum;
        uint2 hp, lp;
        split_pair(v0, v1, hp.x, lp.x);
        split_pair(v2, v3, hp.y, lp.y);
        ah[c >> 2] = hp;
        al[c >> 2] = lp;
        split_pair(ay.x, ay.y, hp.x, lp.x);
        split_pair(ay.z, ay.w, hp.y, lp.y);
        ah[(c >> 2) + 32] = hp;
        al[(c >> 2) + 32] = lp;
    }
}

// ---------------------------------------------------------------------------
// Kernel 2: R8's GEMM verbatim (measured 28.0 us).
// Per CTA: 128 rows x 256 cols. 512 thr = 16 warps (2m x 8n), tile 64x32.
// K in 4 chunks of 64, double-buffered via cp.async.
// ---------------------------------------------------------------------------
#define CH 144
#define O_AH 0
#define O_AL 18432
#define O_BH 36864
#define O_BL 73728
#define BUF 110592
#define G_TOTAL 221184

__global__ __launch_bounds__(512, 1)
void gemm_mma_kernel(const float* __restrict__ gamma,
                     const float* __restrict__ beta,
                     float* __restrict__ out)
{
    extern __shared__ char smem[];
    const uint32_t sb = smem_u32(smem);

    const int tid  = threadIdx.x;
    const int wid  = tid >> 5;
    const int lane = tid & 31;
    const int g    = lane >> 2;
    const int tig  = lane & 3;
    const int mw   = (wid >> 3) * 64;
    const int nw   = wid & 7;
    const int rowBase = blockIdx.x * 128;

    auto load_chunk = [&](int ck, uint32_t bb) {
        const int kof = ck * 64;
#pragma unroll
        for (int i = 0; i < 2; i++) {
            int idx = tid + i * 512;
            int r = idx >> 3, kc = idx & 7;
            const size_t gs = (size_t)(rowBase + r) * KIN + kof + kc * 8;
            uint32_t off = (uint32_t)(r * CH + kc * 16);
            cp_async16(bb + O_AH + off, &g_Ah[gs]);
            cp_async16(bb + O_AL + off, &g_Al[gs]);
        }
#pragma unroll
        for (int i = 0; i < 4; i++) {
            int idx = tid + i * 512;
            int r = idx >> 3, kc = idx & 7;
            const size_t gs = (size_t)r * KIN + kof + kc * 8;
            uint32_t off = (uint32_t)(r * CH + kc * 16);
            cp_async16(bb + O_BH + off, &g_Wh[gs]);
            cp_async16(bb + O_BL + off, &g_Wl[gs]);
        }
        cp_commit();
    };

    load_chunk(0, sb);

    const int quad  = lane >> 3;
    const int lrow  = lane & 7;
    const int aRow  = (quad & 1) * 8 + lrow;
    const int aKoff = (quad >> 1) * 8;
    const int bRow  = ((lane >> 4) * 8) + lrow;
    const int bKoff = ((lane >> 3) & 1) * 8;

    float acc[4][4][4];
#pragma unroll
    for (int mt = 0; mt < 4; mt++)
#pragma unroll
        for (int nt = 0; nt < 4; nt++)
#pragma unroll
            for (int j = 0; j < 4; j++) acc[mt][nt][j] = 0.f;

#pragma unroll 1
    for (int ck = 0; ck < 4; ck++) {
        if (ck < 3) {
            load_chunk(ck + 1, sb + (uint32_t)((ck + 1) & 1) * BUF);
            cp_wait<1>();
        } else {
            cp_wait<0>();
        }
        __syncthreads();

        const uint32_t bb = sb + (uint32_t)(ck & 1) * BUF;
        const uint32_t aBase = bb + O_AH + (uint32_t)((mw + aRow) * CH + aKoff * 2);
        const uint32_t bBase = bb + O_BH + (uint32_t)((nw * 32 + bRow) * CH + bKoff * 2);

#pragma unroll
        for (int ks = 0; ks < 4; ks++) {
            const uint32_t kb = (uint32_t)(ks * 32);
            uint32_t Bh[8], Bl[8];
#pragma unroll
            for (int i = 0; i < 2; i++) {
                uint32_t ba = bBase + (uint32_t)(i * 16 * CH) + kb;
                ldsm_x4(ba, &Bh[i * 4]);
                ldsm_x4(ba + (O_BL - O_BH), &Bl[i * 4]);
            }
#pragma unroll
            for (int mt = 0; mt < 4; mt++) {
                uint32_t Ah[4], Al[4];
                uint32_t aa = aBase + (uint32_t)(mt * 16 * CH) + kb;
                ldsm_x4(aa, Ah);
                ldsm_x4(aa + (O_AL - O_AH), Al);
#pragma unroll
                for (int nt = 0; nt < 4; nt++) {
                    uint32_t b0 = Bh[2 * nt], b1 = Bh[2 * nt + 1];
                    mma_bf16(acc[mt][nt], Ah, b0, b1);
                    mma_bf16(acc[mt][nt], Al, b0, b1);
                    mma_bf16(acc[mt][nt], Ah, Bl[2 * nt], Bl[2 * nt + 1]);
                }
            }
        }
        __syncthreads();
    }

    float* sSum = (float*)smem;
    float* sSq  = sSum + 1024;
    float* sMu  = sSq + 1024;
    float* sRs  = sMu + 128;

#pragma unroll
    for (int mt = 0; mt < 4; mt++)
#pragma unroll
        for (int half = 0; half < 2; half++) {
            float s = 0.f, q = 0.f;
#pragma unroll
            for (int nt = 0; nt < 4; nt++)
#pragma unroll
                for (int j = 0; j < 2; j++) {
                    float v = acc[mt][nt][half * 2 + j];
                    s += v; q += v * v;
                }
            s += __shfl_xor_sync(0xffffffffu, s, 1);
            q += __shfl_xor_sync(0xffffffffu, q, 1);
            s += __shfl_xor_sync(0xffffffffu, s, 2);
            q += __shfl_xor_sync(0xffffffffu, q, 2);
            if (tig == 0) {
                int row = mw + mt * 16 + half * 8 + g;
                sSum[row * 8 + nw] = s;
                sSq[row * 8 + nw]  = q;
            }
        }
    __syncthreads();

    if (tid < 128) {
        float s = 0.f, q = 0.f;
#pragma unroll
        for (int i = 0; i < 8; i++) { s += sSum[tid * 8 + i]; q += sSq[tid * 8 + i]; }
        float mu = s * (1.0f / OD);
        float var = fmaxf(q * (1.0f / OD) - mu * mu, 0.0f);
        sMu[tid] = mu;
        sRs[tid] = rsqrtf(var + LN_EPS);
    }
    __syncthreads();

#pragma unroll
    for (int mt = 0; mt < 4; mt++)
#pragma unroll
        for (int half = 0; half < 2; half++) {
            int row = mw + mt * 16 + half * 8 + g;
            float mu = sMu[row];
            float rs = sRs[row];
            float* orow = out + (size_t)(rowBase + row) * OD;
#pragma unroll
            for (int nt = 0; nt < 4; nt++) {
                int col = nw * 32 + nt * 8 + tig * 2;
                float2 gb0 = *(const float2*)&gamma[col];
                float2 bb0 = *(const float2*)&beta[col];
                float v0 = acc[mt][nt][half * 2 + 0];
                float v1 = acc[mt][nt][half * 2 + 1];
                float2 r2;
                r2.x = fmaxf((v0 - mu) * rs * gb0.x + bb0.x, 0.0f);
                r2.y = fmaxf((v1 - mu) * rs * gb0.y + bb0.y, 0.0f);
                *(float2*)&orow[col] = r2;
            }
        }
}

// ---------------------------------------------------------------------------
extern "C" void kernel_launch(void* const* d_in, const int* in_sizes, int n_in,
                              void* d_out, int out_size)
{
    const float* pos_x   = (const float*)d_in[0];
    const float* xfeat   = (const float*)d_in[1];
    const int*   batch_x = (const int*)  d_in[2];
    const float* pos_y   = (const float*)d_in[3];
    const float* yfeat   = (const float*)d_in[4];
    const int*   batch_y = (const int*)  d_in[5];
    const float* W       = (const float*)d_in[6];
    const float* gamma   = (const float*)d_in[7];
    const float* beta    = (const float*)d_in[8];
    float* out = (float*)d_out;

    prep_kernel<<<16, 1024>>>(W, pos_x, batch_x);
    knn_kernel<<<NY / 64, 256>>>(pos_y, xfeat, batch_x, yfeat, batch_y);

    cudaFuncSetAttribute(gemm_mma_kernel,
                         cudaFuncAttributeMaxDynamicSharedMemorySize, G_TOTAL);
    gemm_mma_kernel<<<NY / 128, 512, G_TOTAL>>>(gamma, beta, out);
}

// round 17
// speedup vs baseline: 1.1468x; 1.0857x over previous
#include <cuda_runtime.h>
#include <cuda_bf16.h>
#include <cstdint>
#include <math.h>

// Problem shapes (fixed)
#define NX 4096
#define NY 16384
#define CX 128
#define CY 128
#define OD 256
#define KIN 256
#define NB 8
#define BIGD 1e30f
#define W_EPS 1e-16f
#define LN_EPS 1e-5f

// Global scratch
__device__ __nv_bfloat16 g_Wh[OD * KIN];
__device__ __nv_bfloat16 g_Wl[OD * KIN];
__device__ float  g_sx[NX];          // per-batch x-sorted x coords
__device__ float4 g_sp4[NX];         // (y, z, |p|^2, idx_bits) same order
__device__ int    g_badsort[NB];
__device__ float  g_Z[NX * OD];      // Z = X @ Wx^T  (exact fp32), 4 MB
__device__ float4 g_w[NY];           // normalized weights (w0,w1,w2,-)
__device__ int4   g_i[NY];           // neighbor indices

// ---------------------------------------------------------------------------
// Helpers (baseline PTX, valid for compute_100)
// ---------------------------------------------------------------------------
static __device__ __forceinline__ uint32_t smem_u32(const void* p) {
    uint32_t a;
    asm("{ .reg .u64 t; cvta.to.shared.u64 t, %1; cvt.u32.u64 %0, t; }"
        : "=r"(a) : "l"(p));
    return a;
}

static __device__ __forceinline__ void ldsm_x4(uint32_t addr, uint32_t* r) {
    asm volatile("ldmatrix.sync.aligned.m8n8.x4.shared.b16 {%0,%1,%2,%3}, [%4];"
                 : "=r"(r[0]), "=r"(r[1]), "=r"(r[2]), "=r"(r[3]) : "r"(addr));
}

static __device__ __forceinline__ void mma_bf16(float* d, const uint32_t* a,
                                                uint32_t b0, uint32_t b1) {
    asm volatile(
        "mma.sync.aligned.m16n8k16.row.col.f32.bf16.bf16.f32 "
        "{%0,%1,%2,%3},{%4,%5,%6,%7},{%8,%9},{%0,%1,%2,%3};"
        : "+f"(d[0]), "+f"(d[1]), "+f"(d[2]), "+f"(d[3])
        : "r"(a[0]), "r"(a[1]), "r"(a[2]), "r"(a[3]), "r"(b0), "r"(b1));
}

static __device__ __forceinline__ void cp_async16(uint32_t dst, const void* src) {
    asm volatile("cp.async.cg.shared.global [%0], [%1], 16;" :: "r"(dst), "l"(src));
}
static __device__ __forceinline__ void cp_commit() {
    asm volatile("cp.async.commit_group;" ::: "memory");
}
template <int N>
static __device__ __forceinline__ void cp_wait() {
    asm volatile("cp.async.wait_group %0;" :: "n"(N) : "memory");
}

// Fast hi/lo bf16 split of a float pair
static __device__ __forceinline__ void split_pair(float v0, float v1,
                                                  uint32_t& hp, uint32_t& lp) {
    uint32_t u0 = __float_as_uint(v0), u1 = __float_as_uint(v1);
    asm("prmt.b32 %0, %1, %2, 0x7632;" : "=r"(hp) : "r"(u0), "r"(u1));
    float h0 = __uint_as_float(u0 & 0xFFFF0000u);
    float h1 = __uint_as_float(u1 & 0xFFFF0000u);
    float l0 = v0 - h0, l1 = v1 - h1;
    asm("cvt.rn.bf16x2.f32 %0, %1, %2;" : "=r"(lp) : "f"(l1), "f"(l0));
}

// Exact branchless top-3 insert
static __device__ __forceinline__ void ins3(float d, int j,
                                            float& d0, float& d1, float& d2,
                                            int& i0, int& i1, int& i2) {
    bool lt0 = d < d0, lt1 = d < d1, lt2 = d < d2;
    d2 = lt1 ? d1 : (lt2 ? d : d2); i2 = lt1 ? i1 : (lt2 ? j : i2);
    d1 = lt0 ? d0 : (lt1 ? d : d1); i1 = lt0 ? i0 : (lt1 ? j : i1);
    d0 = lt0 ? d  : d0;             i0 = lt0 ? j  : i0;
}

static __device__ __forceinline__ uint32_t fkey(float f) {
    uint32_t u = __float_as_uint(f);
    return u ^ (uint32_t)(((int32_t)u >> 31) | 0x80000000);
}

// ---------------------------------------------------------------------------
// Kernel 0 (prep): blocks 0-7 W split; blocks 8-15 per-batch x-sort
// (2-array key/idx bitonic, 1024 threads, 1 elem/thread).
// ---------------------------------------------------------------------------
#define SORT_N 1024

__global__ __launch_bounds__(1024)
void prep_kernel(const float* __restrict__ W,
                 const float* __restrict__ pos_x,
                 const int*   __restrict__ batch_x)
{
    const int tid = threadIdx.x;
    if (blockIdx.x < 8) {
        int base = blockIdx.x * (1024 * 4) + tid;
        uint32_t* wh = (uint32_t*)g_Wh;
        uint32_t* wl = (uint32_t*)g_Wl;
#pragma unroll
        for (int i = 0; i < 4; i++) {
            int p = base + i * 1024;
            float2 v = *(const float2*)&W[p * 2];
            split_pair(v.x, v.y, wh[p], wl[p]);
        }
        return;
    }

    const int b = (int)blockIdx.x - 8;
    __shared__ uint32_t skey[SORT_N];
    __shared__ int      sidx[SORT_N];
    __shared__ int sse[2];
    if (tid < 2) {
        int t = b + tid;
        int lo = 0, hi = NX;
        while (lo < hi) { int m = (lo + hi) >> 1; if (batch_x[m] < t) lo = m + 1; else hi = m; }
        sse[tid] = lo;
    }
    __syncthreads();
    const int s = sse[0], e = sse[1], n = e - s;

    if (n > SORT_N) {
        if (tid == 0) g_badsort[b] = 1;
        for (int i = tid; i < n; i += 1024) {
            int j = s + i;
            float x = pos_x[j * 3], y = pos_x[j * 3 + 1], z = pos_x[j * 3 + 2];
            g_sx[j] = x;
            g_sp4[j] = make_float4(y, z, x * x + y * y + z * z, __int_as_float(j));
        }
        return;
    }
    if (tid == 0) g_badsort[b] = 0;

    if (tid < n) {
        int j = s + tid;
        skey[tid] = fkey(pos_x[j * 3]);
        sidx[tid] = j;
    } else {
        skey[tid] = 0xFFFFFFFFu;
        sidx[tid] = 0;
    }
    __syncthreads();

    for (int k = 2; k <= SORT_N; k <<= 1) {
        for (int jj = k >> 1; jj > 0; jj >>= 1) {
            int l = tid ^ jj;
            if (l > tid) {
                uint32_t ka = skey[tid], kb = skey[l];
                bool up = ((tid & k) == 0);
                if ((ka > kb) == up) {
                    skey[tid] = kb; skey[l] = ka;
                    int t = sidx[tid]; sidx[tid] = sidx[l]; sidx[l] = t;
                }
            }
            __syncthreads();
        }
    }

    if (tid < n) {
        int j = sidx[tid];
        float x = pos_x[j * 3], y = pos_x[j * 3 + 1], z = pos_x[j * 3 + 2];
        g_sx[s + tid] = x;
        g_sp4[s + tid] = make_float4(y, z, x * x + y * y + z * z, __int_as_float(j));
    }
}

// ---------------------------------------------------------------------------
// Kernel 1 (mid): blocks [0,256) pruned quad-KNN -> weights/indices;
//                 blocks [256,512) Z = X @ Wx^T fp32 SGEMM (64x64 tiles).
// 256 threads. Shared union 40960 B (static).
// ---------------------------------------------------------------------------
#define WMAX 2048

__global__ __launch_bounds__(256)
void mid_kernel(const float* __restrict__ pos_y,
                const float* __restrict__ xfeat,
                const int*   __restrict__ batch_x,
                const int*   __restrict__ batch_y,
                const float* __restrict__ W)
{
    __shared__ char sraw[40960];
    __shared__ int sbounds[9];
    __shared__ int sflags;
    const int tid = threadIdx.x;

    if (blockIdx.x >= 256) {
        // ------------------ Z SGEMM part ------------------
        float* sXT = (float*)sraw;                 // [64 k][68 r]
        float* sWT = sXT + 64 * 68;                // [64 k][68 c]
        const int zb = (int)blockIdx.x - 256;
        const int bm = zb >> 2;                    // row tile (64 rows)
        const int bn = zb & 3;                     // col tile (64 cols)
        const int ty = tid >> 4, tx = tid & 15;
        const int r0 = ty * 4, c0 = tx * 4;

        float acc[4][4];
#pragma unroll
        for (int i = 0; i < 4; i++)
#pragma unroll
            for (int j = 0; j < 4; j++) acc[i][j] = 0.f;

#pragma unroll 1
        for (int ck = 0; ck < 2; ck++) {
            for (int idx = tid; idx < 64 * 16; idx += 256) {
                int r = idx >> 4, kc = idx & 15;   // kc: float4 within 64-k chunk
                float4 v = *(const float4*)&xfeat[(size_t)(bm * 64 + r) * CX + ck * 64 + kc * 4];
                sXT[(kc * 4 + 0) * 68 + r] = v.x;
                sXT[(kc * 4 + 1) * 68 + r] = v.y;
                sXT[(kc * 4 + 2) * 68 + r] = v.z;
                sXT[(kc * 4 + 3) * 68 + r] = v.w;
                float4 w = *(const float4*)&W[(size_t)(bn * 64 + r) * KIN + ck * 64 + kc * 4];
                sWT[(kc * 4 + 0) * 68 + r] = w.x;
                sWT[(kc * 4 + 1) * 68 + r] = w.y;
                sWT[(kc * 4 + 2) * 68 + r] = w.z;
                sWT[(kc * 4 + 3) * 68 + r] = w.w;
            }
            __syncthreads();
#pragma unroll 8
            for (int k = 0; k < 64; k++) {
                float4 a = *(const float4*)&sXT[k * 68 + r0];
                float4 w = *(const float4*)&sWT[k * 68 + c0];
                acc[0][0] += a.x * w.x; acc[0][1] += a.x * w.y; acc[0][2] += a.x * w.z; acc[0][3] += a.x * w.w;
                acc[1][0] += a.y * w.x; acc[1][1] += a.y * w.y; acc[1][2] += a.y * w.z; acc[1][3] += a.y * w.w;
                acc[2][0] += a.z * w.x; acc[2][1] += a.z * w.y; acc[2][2] += a.z * w.z; acc[2][3] += a.z * w.w;
                acc[3][0] += a.w * w.x; acc[3][1] += a.w * w.y; acc[3][2] += a.w * w.z; acc[3][3] += a.w * w.w;
            }
            __syncthreads();
        }

#pragma unroll
        for (int i = 0; i < 4; i++) {
            float4 v = make_float4(acc[i][0], acc[i][1], acc[i][2], acc[i][3]);
            *(float4*)&g_Z[(size_t)(bm * 64 + r0 + i) * OD + bn * 64 + c0] = v;
        }
        return;
    }

    // ------------------ KNN part ------------------
    float*  sxA  = (float*)sraw;                   // [2048]
    float4* sp4A = (float4*)(sraw + 8192);         // [2048]

    if (tid < 9) {
        int t = tid;
        int lo = 0, hi = NX;
        while (lo < hi) { int m = (lo + hi) >> 1; if (batch_x[m] < t) lo = m + 1; else hi = m; }
        sbounds[t] = lo;
    }
    __syncthreads();

    const int q0   = blockIdx.x * 64;
    const int bmin = batch_y[q0];
    const int bmax = batch_y[q0 + 63];
    const int s0   = sbounds[bmin];
    const int n    = sbounds[bmax + 1] - s0;

    if (tid == 0) {
        int bad = 0;
        for (int b = bmin; b <= bmax; b++) bad |= g_badsort[b];
        sflags = bad;
    }

    const bool fit = (n <= WMAX);
    if (fit) {
        for (int i = tid; i < n; i += 256) {
            sxA[i] = g_sx[s0 + i];
            sp4A[i] = g_sp4[s0 + i];
        }
    }
    __syncthreads();
    const bool pruned = fit && (sflags == 0);

    const int qIdx = tid >> 2;
    const int g4   = tid & 3;
    const int yi   = q0 + qIdx;

    const float qx = pos_y[yi * 3 + 0];
    const float qy = pos_y[yi * 3 + 1];
    const float qz = pos_y[yi * 3 + 2];
    const float qn = qx * qx + qy * qy + qz * qz;
    const int b = batch_y[yi];
    const int s = sbounds[b], e = sbounds[b + 1];

    float d0 = BIGD, d1 = BIGD, d2v = BIGD;
    int   i0 = 0,    i1 = 0,    i2 = 0;

    if (pruned) {
        const int ls = s - s0, le = e - s0;
        int lo = ls, hi = le;
        while (lo < hi) { int m = (lo + hi) >> 1; if (sxA[m] < qx) lo = m + 1; else hi = m; }
        const int pos = lo;
        int j, stride;
        if (g4 < 2) { j = pos - 1 - (g4 & 1); stride = -2; }
        else        { j = pos + (g4 & 1);     stride = 2;  }
        const unsigned span = (unsigned)(le - ls);
        while ((unsigned)(j - ls) < span) {
            float dx = sxA[j] - qx;
            if (dx * dx > d2v + 4e-6f) break;
            float4 p = sp4A[j];
            float d = fmaxf(qn + p.z - 2.0f * (qx * sxA[j] + qy * p.x + qz * p.y), 0.0f);
            ins3(d, __float_as_int(p.w), d0, d1, d2v, i0, i1, i2);
            j += stride;
        }
    } else {
        for (int j = s + g4; j < e; j += 4) {
            float xj = g_sx[j];
            float4 p = g_sp4[j];
            float d = fmaxf(qn + p.z - 2.0f * (qx * xj + qy * p.x + qz * p.y), 0.0f);
            ins3(d, __float_as_int(p.w), d0, d1, d2v, i0, i1, i2);
        }
    }

#pragma unroll
    for (int off = 1; off <= 2; off <<= 1) {
        float od0 = __shfl_xor_sync(0xffffffffu, d0,  off);
        float od1 = __shfl_xor_sync(0xffffffffu, d1,  off);
        float od2 = __shfl_xor_sync(0xffffffffu, d2v, off);
        int   oi0 = __shfl_xor_sync(0xffffffffu, i0,  off);
        int   oi1 = __shfl_xor_sync(0xffffffffu, i1,  off);
        int   oi2 = __shfl_xor_sync(0xffffffffu, i2,  off);
        ins3(od0, oi0, d0, d1, d2v, i0, i1, i2);
        ins3(od1, oi1, d0, d1, d2v, i0, i1, i2);
        ins3(od2, oi2, d0, d1, d2v, i0, i1, i2);
    }

    if (g4 == 0) {
        float w0 = 1.0f / fmaxf(d0,  W_EPS);
        float w1 = 1.0f / fmaxf(d1,  W_EPS);
        float w2 = 1.0f / fmaxf(d2v, W_EPS);
        float inv = 1.0f / (w0 + w1 + w2);
        g_w[yi] = make_float4(w0 * inv, w1 * inv, w2 * inv, 0.f);
        g_i[yi] = make_int4(i0, i1, i2, 0);
    }
}

// ---------------------------------------------------------------------------
// Kernel 2: h = y @ Wy^T (3-term bf16, K=128) + S@Z combine + LN + ReLU.
// 128 CTAs x 512 thr, 16 warps (2m x 8n), warp tile 64x32.
// SMEM (155648): A_hi@0 (34816), A_lo@34816, B x2 @69632 (40960 each),
//                sW4@151552 (2048), sI4@153600 (2048)
// ---------------------------------------------------------------------------
#define SROW2 272
#define A2_HI 0
#define A2_LO 34816
#define B2 69632
#define B2BUF 40960
#define B2LOF 20480
#define BSTR 80
#define WI_W 151552
#define WI_I 153600
#define G2_TOTAL 155648

__global__ __launch_bounds__(512, 1)
void gemm2_kernel(const float* __restrict__ yfeat,
                  const float* __restrict__ gamma,
                  const float* __restrict__ beta,
                  float* __restrict__ out)
{
    extern __shared__ char smem[];
    const uint32_t sb = smem_u32(smem);

    const int tid  = threadIdx.x;
    const int wid  = tid >> 5;
    const int lane = tid & 31;
    const int rowBase = blockIdx.x * 128;

    // B loader: Wy = W cols [128,256)
    auto load_B = [&](int p, uint32_t bb) {
        const int kof = 128 + p * 32;
#pragma unroll
        for (int i = 0; i < 2; i++) {
            int idx = tid + i * 512;
            int r = idx >> 2, kc = idx & 3;
            const size_t gs = (size_t)r * KIN + kof + kc * 8;
            uint32_t off = (uint32_t)(r * BSTR + kc * 16);
            cp_async16(bb + off, &g_Wh[gs]);
            cp_async16(bb + B2LOF + off, &g_Wl[gs]);
        }
        cp_commit();
    };

    load_B(0, sb + B2);

    // load weights/indices
    if (tid < 128) {
        *(float4*)(smem + WI_W + tid * 16) = g_w[rowBase + tid];
        *(int4*)(smem + WI_I + tid * 16) = g_i[rowBase + tid];
    }

    // ---- A tile: yfeat 128 rows x 128 K, split bf16 hi/lo ----
#pragma unroll
    for (int i = 0; i < 4; i++) {
        int idx = tid + i * 512;                 // 0..2047
        int r = idx >> 4, kc = idx & 15;         // 16 8-elem chunks per row
        const float* src = &yfeat[(size_t)(rowBase + r) * CY + kc * 8];
        float4 v0 = *(const float4*)src;
        float4 v1 = *(const float4*)(src + 4);
        uint2 hp, lp, hq, lq;
        split_pair(v0.x, v0.y, hp.x, lp.x);
        split_pair(v0.z, v0.w, hp.y, lp.y);
        split_pair(v1.x, v1.y, hq.x, lq.x);
        split_pair(v1.z, v1.w, hq.y, lq.y);
        uint32_t off = (uint32_t)(r * SROW2 + kc * 16);
        *(uint2*)(smem + A2_HI + off) = hp;
        *(uint2*)(smem + A2_HI + off + 8) = hq;
        *(uint2*)(smem + A2_LO + off) = lp;
        *(uint2*)(smem + A2_LO + off + 8) = lq;
    }

    // ---- GEMM: 4 phases of K=32 ----
    const int g   = lane >> 2;
    const int tig = lane & 3;
    const int mw  = (wid >> 3) * 64;
    const int nw  = wid & 7;

    const int quad  = lane >> 3;
    const int lrow  = lane & 7;
    const int aRow  = (quad & 1) * 8 + lrow;
    const int aKoff = (quad >> 1) * 8;
    const int bRow  = ((lane >> 4) * 8) + lrow;
    const int bKoff = ((lane >> 3) & 1) * 8;
    const uint32_t offB = (uint32_t)((nw * 32 + bRow) * BSTR + bKoff * 2);
    const uint32_t aCol = (uint32_t)((mw + aRow) * SROW2 + aKoff * 2);

    float acc[4][4][4];
#pragma unroll
    for (int mt = 0; mt < 4; mt++)
#pragma unroll
        for (int nt = 0; nt < 4; nt++)
#pragma unroll
            for (int j = 0; j < 4; j++) acc[mt][nt][j] = 0.f;

#pragma unroll 1
    for (int p = 0; p < 4; p++) {
        if (p < 3) {
            load_B(p + 1, sb + B2 + (uint32_t)((p + 1) & 1) * B2BUF);
            cp_wait<1>();
        } else {
            cp_wait<0>();
        }
        __syncthreads();

        const uint32_t bB = sb + B2 + (uint32_t)(p & 1) * B2BUF + offB;
        const uint32_t aB = sb + A2_HI + aCol + (uint32_t)(p * 64);

#pragma unroll
        for (int ks = 0; ks < 2; ks++) {
            const uint32_t kb = (uint32_t)(ks * 32);
            uint32_t Bh[8], Bl[8];
            ldsm_x4(bB + kb, Bh);
            ldsm_x4(bB + 1280 + kb, Bh + 4);
            ldsm_x4(bB + B2LOF + kb, Bl);
            ldsm_x4(bB + B2LOF + 1280 + kb, Bl + 4);
#pragma unroll
            for (int mt = 0; mt < 4; mt++) {
                uint32_t Ah[4], Al[4];
                const uint32_t aa = aB + (uint32_t)(mt * 16 * SROW2) + kb;
                ldsm_x4(aa, Ah);
                ldsm_x4(aa + (A2_LO - A2_HI), Al);
#pragma unroll
                for (int nt = 0; nt < 4; nt++)
                    mma_bf16(acc[mt][nt], Ah, Bh[2 * nt], Bh[2 * nt + 1]);
#pragma unroll
                for (int nt = 0; nt < 4; nt++)
                    mma_bf16(acc[mt][nt], Al, Bh[2 * nt], Bh[2 * nt + 1]);
#pragma unroll
                for (int nt = 0; nt < 4; nt++)
                    mma_bf16(acc[mt][nt], Ah, Bl[2 * nt], Bl[2 * nt + 1]);
            }
        }
        __syncthreads();
    }

    // ---- combine: acc += w0*Z[i0] + w1*Z[i1] + w2*Z[i2] ----
#pragma unroll
    for (int mt = 0; mt < 4; mt++)
#pragma unroll
        for (int half = 0; half < 2; half++) {
            int row = mw + mt * 16 + half * 8 + g;
            float4 wv = *(const float4*)(smem + WI_W + row * 16);
            int4   iv = *(const int4*)(smem + WI_I + row * 16);
            const float* z0 = g_Z + (size_t)iv.x * OD;
            const float* z1 = g_Z + (size_t)iv.y * OD;
            const float* z2 = g_Z + (size_t)iv.z * OD;
#pragma unroll
            for (int nt = 0; nt < 4; nt++) {
                int col = nw * 32 + nt * 8 + tig * 2;
                float2 a = *(const float2*)&z0[col];
                float2 bz = *(const float2*)&z1[col];
                float2 c = *(const float2*)&z2[col];
                acc[mt][nt][half * 2 + 0] += wv.x * a.x + wv.y * bz.x + wv.z * c.x;
                acc[mt][nt][half * 2 + 1] += wv.x * a.y + wv.y * bz.y + wv.z * c.y;
            }
        }

    // ---- LayerNorm stats (overlay B region) ----
    float* sSum = (float*)(smem + B2);
    float* sSq  = sSum + 1024;
    float* sMu  = sSq + 1024;
    float* sRs  = sMu + 128;

#pragma unroll
    for (int mt = 0; mt < 4; mt++)
#pragma unroll
        for (int half = 0; half < 2; half++) {
            float s = 0.f, q = 0.f;
#pragma unroll
            for (int nt = 0; nt < 4; nt++)
#pragma unroll
                for (int j = 0; j < 2; j++) {
                    float v = acc[mt][nt][half * 2 + j];
                    s += v; q += v * v;
                }
            s += __shfl_xor_sync(0xffffffffu, s, 1);
            q += __shfl_xor_sync(0xffffffffu, q, 1);
            s += __shfl_xor_sync(0xffffffffu, s, 2);
            q += __shfl_xor_sync(0xffffffffu, q, 2);
            if (tig == 0) {
                int row = mw + mt * 16 + half * 8 + g;
                sSum[row * 8 + nw] = s;
                sSq[row * 8 + nw]  = q;
            }
        }
    __syncthreads();

    if (tid < 128) {
        float s = 0.f, q = 0.f;
#pragma unroll
        for (int i = 0; i < 8; i++) { s += sSum[tid * 8 + i]; q += sSq[tid * 8 + i]; }
        float mu = s * (1.0f / OD);
        float var = fmaxf(q * (1.0f / OD) - mu * mu, 0.0f);
        sMu[tid] = mu;
        sRs[tid] = rsqrtf(var + LN_EPS);
    }
    __syncthreads();

    // ---- normalize + affine + ReLU + store ----
#pragma unroll
    for (int mt = 0; mt < 4; mt++)
#pragma unroll
        for (int half = 0; half < 2; half++) {
            int row = mw + mt * 16 + half * 8 + g;
            float mu = sMu[row];
            float rs = sRs[row];
            float* orow = out + (size_t)(rowBase + row) * OD;
#pragma unroll
            for (int nt = 0; nt < 4; nt++) {
                int col = nw * 32 + nt * 8 + tig * 2;
                float2 gb0 = *(const float2*)&gamma[col];
                float2 bb0 = *(const float2*)&beta[col];
                float v0 = acc[mt][nt][half * 2 + 0];
                float v1 = acc[mt][nt][half * 2 + 1];
                float2 r2;
                r2.x = fmaxf((v0 - mu) * rs * gb0.x + bb0.x, 0.0f);
                r2.y = fmaxf((v1 - mu) * rs * gb0.y + bb0.y, 0.0f);
                *(float2*)&orow[col] = r2;
            }
        }
}

// ---------------------------------------------------------------------------
extern "C" void kernel_launch(void* const* d_in, const int* in_sizes, int n_in,
                              void* d_out, int out_size)
{
    const float* pos_x   = (const float*)d_in[0];
    const float* xfeat   = (const float*)d_in[1];
    const int*   batch_x = (const int*)  d_in[2];
    const float* pos_y   = (const float*)d_in[3];
    const float* yfeat   = (const float*)d_in[4];
    const int*   batch_y = (const int*)  d_in[5];
    const float* W       = (const float*)d_in[6];
    const float* gamma   = (const float*)d_in[7];
    const float* beta    = (const float*)d_in[8];
    float* out = (float*)d_out;

    prep_kernel<<<16, 1024>>>(W, pos_x, batch_x);
    mid_kernel<<<512, 256>>>(pos_y, xfeat, batch_x, batch_y, W);

    cudaFuncSetAttribute(gemm2_kernel,
                         cudaFuncAttributeMaxDynamicSharedMemorySize, G2_TOTAL);
    gemm2_kernel<<<NY / 128, 512, G2_TOTAL>>>(yfeat, gamma, beta, out);
}